// round 7
// baseline (speedup 1.0000x reference)
#include <cuda_runtime.h>
#include <cuda_fp16.h>
#include <cstdint>

// ---------------- problem constants ----------------
#define NQ      8
#define EMBED   512
#define FFN     2048
#define KC      128           // K-chunk over FFN
#define NCHUNK  16            // FFN / KC
#define THREADS 256
#define NCTAS   512           // 256 token tiles x 2 N-halves

// ---------------- smem layout (bytes) ----------------
#define SM_W1   0             // 2 x 8192  (duplicated f32 pairs, 128 f x 8 q)
#define SM_H    16384         // 128 rows x 256B fp16 (swizzled)
#define SM_B    49152         // 2 x 65536 (256 rows x 256B fp16, swizzled)
#define SMEM_TOTAL 180224

// fp16 copy of W2 — __device__ global scratch (allowed path)
__device__ __half g_W2h[EMBED * FFN];

// ---------------- helpers ----------------
__device__ __forceinline__ uint32_t smem_u32(const void* p) {
    uint32_t a;
    asm("{ .reg .u64 t; cvta.to.shared.u64 t, %1; cvt.u32.u64 %0, t; }" : "=r"(a) : "l"(p));
    return a;
}
__device__ __forceinline__ uint32_t lds32(uint32_t a) {
    uint32_t v;
    asm volatile("ld.shared.b32 %0, [%1];" : "=r"(v) : "r"(a));
    return v;
}

#define CP_ASYNC_16(dst, src) \
    asm volatile("cp.async.cg.shared.global [%0], [%1], 16;" :: "r"((uint32_t)(dst)), "l"(src) : "memory")
#define CP_COMMIT() asm volatile("cp.async.commit_group;" ::: "memory")

// packed f32x2 helpers (validated supported on sm_103 base in R4 compile)
__device__ __forceinline__ unsigned long long pk2(float lo, float hi) {
    unsigned long long d; asm("mov.b64 %0, {%1, %2};" : "=l"(d) : "f"(lo), "f"(hi)); return d;
}
__device__ __forceinline__ unsigned long long fma2(unsigned long long a, unsigned long long b,
                                                   unsigned long long c) {
    unsigned long long d; asm("fma.rn.f32x2 %0, %1, %2, %3;" : "=l"(d) : "l"(a), "l"(b), "l"(c));
    return d;
}
__device__ __forceinline__ void unpk2(float& lo, float& hi, unsigned long long v) {
    asm("mov.b64 {%0, %1}, %2;" : "=f"(lo), "=f"(hi) : "l"(v));
}

// mma.sync m16n8k16 row.col f32 += f16*f16
__device__ __forceinline__ void hmma(float* d, const uint32_t* a, const uint32_t* b) {
    asm volatile("mma.sync.aligned.m16n8k16.row.col.f32.f16.f16.f32 "
                 "{%0,%1,%2,%3}, {%4,%5,%6,%7}, {%8,%9}, {%0,%1,%2,%3};"
                 : "+f"(d[0]), "+f"(d[1]), "+f"(d[2]), "+f"(d[3])
                 : "r"(a[0]), "r"(a[1]), "r"(a[2]), "r"(a[3]), "r"(b[0]), "r"(b[1]));
}

// ---------------- W2 fp32 -> fp16 ----------------
__global__ void __launch_bounds__(256) w2cvt_kernel(const float* __restrict__ W2) {
    size_t i = ((size_t)blockIdx.x * blockDim.x + threadIdx.x) * 4;
    float4 v = *reinterpret_cast<const float4*>(W2 + i);
    __half2* d = reinterpret_cast<__half2*>(g_W2h + i);
    d[0] = __floats2half2_rn(v.x, v.y);
    d[1] = __floats2half2_rn(v.z, v.w);
}

// ---------------- fused main kernel ----------------
__global__ void __launch_bounds__(THREADS, 1)
ffq_mma(const float* __restrict__ x, const float* __restrict__ theta,
        const float* __restrict__ W1, float* __restrict__ out) {
    extern __shared__ char smem[];
    const uint32_t sb = smem_u32(smem);
    const int tid   = threadIdx.x;
    const int lane  = tid & 31;
    const int warp  = tid >> 5;
    const int tile  = blockIdx.x >> 1;
    const int nhalf = blockIdx.x & 1;

    // h-compute identity: thread owns tokens {tg, tg+32, tg+64, tg+96} x 16 f (fg)
    const int tg = lane;          // token group 0..31 (per warp all tokens covered)
    const int fg = warp;          // f-group 0..7 (16 f each)

    // MMA identity: 8 warps as 2(M) x 4(N), warp tile 64x64
    const int mrow0 = (warp & 1) * 64;
    const int n0    = (warp >> 1) * 64;

    // ---- quantum features: 4 tokens, packed f32x2 over (t, t+32) / (t+64, t+96) ----
    unsigned long long qqA[NQ], qqB[NQ];
    {
        float th[NQ];
        #pragma unroll
        for (int i = 0; i < NQ; i++) th[i] = theta[i];
        float qv[4][NQ];
        #pragma unroll
        for (int tt = 0; tt < 4; tt++) {
            const float* xp = x + ((size_t)tile * 128 + tg + tt * 32) * EMBED;
            float4 v0 = *reinterpret_cast<const float4*>(xp);
            float4 v1 = *reinterpret_cast<const float4*>(xp + 4);
            float xv[NQ] = {v0.x, v0.y, v0.z, v0.w, v1.x, v1.y, v1.z, v1.w};
            #pragma unroll
            for (int i = 0; i < NQ; i++) qv[tt][i] = cosf(2.0f * xv[i] + th[i]);
        }
        #pragma unroll
        for (int i = 0; i < NQ; i++) {
            qqA[i] = pk2(qv[0][i], qv[1][i]);
            qqB[i] = pk2(qv[2][i], qv[3][i]);
        }
    }

    // accumulators: 4 m16 x 8 n8 x 4 f32 = 128 regs
    float acc[4][8][4];
    #pragma unroll
    for (int mb = 0; mb < 4; mb++)
        #pragma unroll
        for (int nb = 0; nb < 8; nb++)
            #pragma unroll
            for (int i = 0; i < 4; i++) acc[mb][nb][i] = 0.0f;

    // ---- prologue: W1 slice 0 in regs; issue cp.async for B chunk 0 ----
    float4 w1r = *reinterpret_cast<const float4*>(W1 + tid * 4);
    {
        const char* src = (const char*)g_W2h + ((size_t)(nhalf * 256 + tid) * FFN) * 2;
        uint32_t dstrow = sb + SM_B + tid * 256;
        uint32_t sw = (tid & 15) << 4;
        #pragma unroll
        for (int cc = 0; cc < 16; cc++)
            CP_ASYNC_16(dstrow + ((cc * 16) ^ sw), src + cc * 16);
        CP_COMMIT();
    }

    for (int k = 0; k < NCHUNK; k++) {
        const int s = k & 1;

        // ---- store W1 slice k (duplicated f32 pairs for fma2 broadcast) ----
        {
            uint32_t wdst = sb + SM_W1 + s * 8192 + tid * 32;
            asm volatile("st.shared.v4.f32 [%0], {%1,%1,%2,%2};"
                         :: "r"(wdst), "f"(w1r.x), "f"(w1r.y) : "memory");
            asm volatile("st.shared.v4.f32 [%0], {%1,%1,%2,%2};"
                         :: "r"(wdst + 16), "f"(w1r.z), "f"(w1r.w) : "memory");
        }

        // ---- issue cp.async for B chunk k+1 (safe: barrier at end of prev iter) ----
        if (k + 1 < NCHUNK) {
            const char* src = (const char*)g_W2h +
                ((size_t)(nhalf * 256 + tid) * FFN + (size_t)(k + 1) * KC) * 2;
            uint32_t dstrow = sb + SM_B + (s ^ 1) * 65536 + tid * 256;
            uint32_t sw = (tid & 15) << 4;
            #pragma unroll
            for (int cc = 0; cc < 16; cc++)
                CP_ASYNC_16(dstrow + ((cc * 16) ^ sw), src + cc * 16);
            CP_COMMIT();
        }

        __syncthreads();   // W1 slice visible

        // ---- h chunk: z = q . W1^T, relu, fp16, swizzled smem store ----
        {
            const uint32_t w1b = sb + SM_W1 + s * 8192;
            #pragma unroll
            for (int jh = 0; jh < 2; jh++) {
                unsigned long long aA[8], aB[8];
                #pragma unroll
                for (int j = 0; j < 8; j++) {
                    uint32_t wa = w1b + (fg * 16 + jh * 8 + j) * 64;
                    unsigned long long d0, d1, d2, d3, d4, d5, d6, d7;
                    asm volatile("ld.shared.v2.b64 {%0,%1}, [%2];" : "=l"(d0), "=l"(d1) : "r"(wa));
                    asm volatile("ld.shared.v2.b64 {%0,%1}, [%2];" : "=l"(d2), "=l"(d3) : "r"(wa + 16));
                    asm volatile("ld.shared.v2.b64 {%0,%1}, [%2];" : "=l"(d4), "=l"(d5) : "r"(wa + 32));
                    asm volatile("ld.shared.v2.b64 {%0,%1}, [%2];" : "=l"(d6), "=l"(d7) : "r"(wa + 48));
                    unsigned long long a = fma2(qqA[0], d0, 0ull);
                    a = fma2(qqA[1], d1, a); a = fma2(qqA[2], d2, a); a = fma2(qqA[3], d3, a);
                    a = fma2(qqA[4], d4, a); a = fma2(qqA[5], d5, a);
                    a = fma2(qqA[6], d6, a); a = fma2(qqA[7], d7, a);
                    aA[j] = a;
                    unsigned long long b = fma2(qqB[0], d0, 0ull);
                    b = fma2(qqB[1], d1, b); b = fma2(qqB[2], d2, b); b = fma2(qqB[3], d3, b);
                    b = fma2(qqB[4], d4, b); b = fma2(qqB[5], d5, b);
                    b = fma2(qqB[6], d6, b); b = fma2(qqB[7], d7, b);
                    aB[j] = b;
                }
                // convert + store: 4 tokens x 8 f (16B each)
                uint32_t u0[4], u1[4], u2[4], u3[4];
                #pragma unroll
                for (int j = 0; j < 4; j++) {
                    float za0, za1, zb0, zb1;
                    unpk2(za0, za1, aA[2 * j]); unpk2(zb0, zb1, aA[2 * j + 1]);
                    __half2 h0 = __floats2half2_rn(fmaxf(za0, 0.f), fmaxf(zb0, 0.f));
                    __half2 h1 = __floats2half2_rn(fmaxf(za1, 0.f), fmaxf(zb1, 0.f));
                    u0[j] = *reinterpret_cast<uint32_t*>(&h0);
                    u1[j] = *reinterpret_cast<uint32_t*>(&h1);
                    unpk2(za0, za1, aB[2 * j]); unpk2(zb0, zb1, aB[2 * j + 1]);
                    __half2 h2 = __floats2half2_rn(fmaxf(za0, 0.f), fmaxf(zb0, 0.f));
                    __half2 h3 = __floats2half2_rn(fmaxf(za1, 0.f), fmaxf(zb1, 0.f));
                    u2[j] = *reinterpret_cast<uint32_t*>(&h2);
                    u3[j] = *reinterpret_cast<uint32_t*>(&h3);
                }
                const uint32_t colb = fg * 32 + jh * 16;
                #pragma unroll
                for (int tt = 0; tt < 4; tt++) {
                    int t = tg + tt * 32;
                    uint32_t addr = sb + SM_H + t * 256 + (colb ^ ((t & 15) << 4));
                    const uint32_t* u = (tt == 0) ? u0 : (tt == 1) ? u1 : (tt == 2) ? u2 : u3;
                    asm volatile("st.shared.v4.b32 [%0], {%1,%2,%3,%4};"
                                 :: "r"(addr), "r"(u[0]), "r"(u[1]), "r"(u[2]), "r"(u[3]) : "memory");
                }
            }
        }

        // ---- prefetch W1 slice k+1 ----
        if (k + 1 < NCHUNK)
            w1r = *reinterpret_cast<const float4*>(W1 + (size_t)(k + 1) * KC * NQ + tid * 4);

        if (k + 1 < NCHUNK) { asm volatile("cp.async.wait_group 1;" ::: "memory"); }
        else                { asm volatile("cp.async.wait_group 0;" ::: "memory"); }
        __syncthreads();   // h + B(k) visible

        // ---- MMA phase: 8 k16 steps ----
        {
            const uint32_t hb  = sb + SM_H;
            const uint32_t bbf = sb + SM_B + s * 65536;
            #pragma unroll
            for (int kk = 0; kk < 8; kk++) {
                const uint32_t cb = kk * 32 + (lane & 3) * 4;
                uint32_t Bf[8][2];
                #pragma unroll
                for (int nb = 0; nb < 8; nb++) {
                    int n = n0 + nb * 8 + (lane >> 2);
                    uint32_t sw = (n & 15) << 4;
                    uint32_t base = bbf + n * 256;
                    Bf[nb][0] = lds32(base + (cb ^ sw));
                    Bf[nb][1] = lds32(base + ((cb + 16) ^ sw));
                }
                #pragma unroll
                for (int mb = 0; mb < 4; mb++) {
                    int r0 = mrow0 + mb * 16 + (lane >> 2);
                    int r1 = r0 + 8;
                    uint32_t sw0 = (r0 & 15) << 4, sw1 = (r1 & 15) << 4;
                    uint32_t A[4];
                    A[0] = lds32(hb + r0 * 256 + (cb ^ sw0));
                    A[1] = lds32(hb + r1 * 256 + (cb ^ sw1));
                    A[2] = lds32(hb + r0 * 256 + ((cb + 16) ^ sw0));
                    A[3] = lds32(hb + r1 * 256 + ((cb + 16) ^ sw1));
                    #pragma unroll
                    for (int nb = 0; nb < 8; nb++)
                        hmma(acc[mb][nb], A, Bf[nb]);
                }
            }
        }

        __syncthreads();   // protects h buffer + B slot reuse next iter
    }

    // ---- epilogue: write out ----
    #pragma unroll
    for (int mb = 0; mb < 4; mb++) {
        int r = mrow0 + mb * 16 + (lane >> 2);
        size_t gt = (size_t)tile * 128 + r;
        float* row0 = out + gt * EMBED + nhalf * 256;
        float* row1 = row0 + 8 * EMBED;
        #pragma unroll
        for (int nb = 0; nb < 8; nb++) {
            int c = n0 + nb * 8 + (lane & 3) * 2;
            float2 v0 = make_float2(acc[mb][nb][0], acc[mb][nb][1]);
            float2 v1 = make_float2(acc[mb][nb][2], acc[mb][nb][3]);
            *reinterpret_cast<float2*>(row0 + c) = v0;
            *reinterpret_cast<float2*>(row1 + c) = v1;
        }
    }
}

// ---------------- launch ----------------
extern "C" void kernel_launch(void* const* d_in, const int* in_sizes, int n_in,
                              void* d_out, int out_size) {
    const float* x     = (const float*)d_in[0];
    const float* theta = (const float*)d_in[1];
    const float* W1    = (const float*)d_in[2];
    const float* W2    = (const float*)d_in[3];
    float* out = (float*)d_out;

    cudaFuncSetAttribute(ffq_mma, cudaFuncAttributeMaxDynamicSharedMemorySize, SMEM_TOTAL);

    // W2 fp32 -> fp16 (2 MB scratch, deterministic each call)
    w2cvt_kernel<<<(EMBED * FFN) / (256 * 4), 256>>>(W2);

    // fused GEMM: 512 CTAs = 256 token tiles x 2 N-halves
    ffq_mma<<<NCTAS, THREADS, SMEM_TOTAL>>>(x, theta, W1, out);
}